// round 7
// baseline (speedup 1.0000x reference)
#include <cuda_runtime.h>
#include <cstdint>
#include <cstddef>

#define T_STEPS 512
#define BATCH   64
#define HID     1024
#define G4      4096
#define M1      (T_STEPS * BATCH)   // 32768
#define NCTA    128

// ---------------- device scratch (no allocs allowed) ----------------
__device__ float    g_xpre[(size_t)M1 * G4];      // 512 MB: [T*B, 4H]
__device__ float    g_hbuf[2][BATCH * HID];       // double-buffered h, A-fragment-major layout
__device__ unsigned g_cnt1[16];                   // tree barrier: 16 groups of 8 CTAs
__device__ unsigned g_cnt2;                       // tree barrier: root (16 leaders)
__device__ unsigned g_gen;                        // monotonic generation

// ---------------- helpers ----------------
__device__ __forceinline__ uint32_t f2tf32(float x) {
    uint32_t r;
    asm("cvt.rna.tf32.f32 %0, %1;" : "=r"(r) : "f"(x));
    return r;
}

__device__ __forceinline__ void mma_tf32(float* c, const uint32_t* a, const uint32_t* b) {
    asm volatile(
        "mma.sync.aligned.m16n8k8.row.col.f32.tf32.tf32.f32 "
        "{%0,%1,%2,%3}, {%4,%5,%6,%7}, {%8,%9}, {%0,%1,%2,%3};"
        : "+f"(c[0]), "+f"(c[1]), "+f"(c[2]), "+f"(c[3])
        : "r"(a[0]), "r"(a[1]), "r"(a[2]), "r"(a[3]), "r"(b[0]), "r"(b[1]));
}

// L2-only vector load, pinned in place by asm volatile (ptxas cannot rematerialize)
__device__ __forceinline__ uint4 ldg128_cg(const void* p) {
    uint4 v;
    asm volatile("ld.global.cg.v4.u32 {%0,%1,%2,%3}, [%4];"
                 : "=r"(v.x), "=r"(v.y), "=r"(v.z), "=r"(v.w) : "l"(p));
    return v;
}

// ---------------- phase 1: x_pre = input @ W_ih^T + b_ih + b_hh (tf32 mma) ----------------
// CTA tile 128x128, 8 warps in 4(M) x 2(N), warp tile 32x64. K-chunk 16, 2-stage pipeline.
__global__ __launch_bounds__(256) void gemm1_k(
    const float* __restrict__ A, const float* __restrict__ W,
    const float* __restrict__ bih, const float* __restrict__ bhh) {
    __shared__ uint32_t As[2][128][20];
    __shared__ uint32_t Bs[2][128][20];

    const int tid   = threadIdx.x;
    const int lane  = tid & 31;
    const int wid   = tid >> 5;
    const int warpM = wid & 3;
    const int warpN = wid >> 2;
    const int m0 = blockIdx.y * 128;
    const int n0 = blockIdx.x * 128;

    const int r1 = tid >> 2;
    const int r2 = r1 + 64;
    const int c4 = (tid & 3) * 4;

    float acc[2][8][4];
#pragma unroll
    for (int mt = 0; mt < 2; mt++)
#pragma unroll
        for (int nt = 0; nt < 8; nt++)
#pragma unroll
            for (int r = 0; r < 4; r++) acc[mt][nt][r] = 0.0f;

    const float* Ap1 = A + (size_t)(m0 + r1) * 1024 + c4;
    const float* Ap2 = A + (size_t)(m0 + r2) * 1024 + c4;
    const float* Wp1 = W + (size_t)(n0 + r1) * 1024 + c4;
    const float* Wp2 = W + (size_t)(n0 + r2) * 1024 + c4;

    const int g  = lane >> 2;
    const int tg = lane & 3;

    float4 ra1, ra2, rb1, rb2;

    ra1 = *(const float4*)(Ap1);
    ra2 = *(const float4*)(Ap2);
    rb1 = *(const float4*)(Wp1);
    rb2 = *(const float4*)(Wp2);
    {
        uint4 u;
        u.x = f2tf32(ra1.x); u.y = f2tf32(ra1.y); u.z = f2tf32(ra1.z); u.w = f2tf32(ra1.w);
        *(uint4*)&As[0][r1][c4] = u;
        u.x = f2tf32(ra2.x); u.y = f2tf32(ra2.y); u.z = f2tf32(ra2.z); u.w = f2tf32(ra2.w);
        *(uint4*)&As[0][r2][c4] = u;
        u.x = f2tf32(rb1.x); u.y = f2tf32(rb1.y); u.z = f2tf32(rb1.z); u.w = f2tf32(rb1.w);
        *(uint4*)&Bs[0][r1][c4] = u;
        u.x = f2tf32(rb2.x); u.y = f2tf32(rb2.y); u.z = f2tf32(rb2.z); u.w = f2tf32(rb2.w);
        *(uint4*)&Bs[0][r2][c4] = u;
    }
    __syncthreads();

    for (int k = 0; k < 64; k++) {
        if (k < 63) {
            const int off = (k + 1) * 16;
            ra1 = *(const float4*)(Ap1 + off);
            ra2 = *(const float4*)(Ap2 + off);
            rb1 = *(const float4*)(Wp1 + off);
            rb2 = *(const float4*)(Wp2 + off);
        }
        const int cur = k & 1;

#pragma unroll
        for (int ksl = 0; ksl < 2; ksl++) {
            const int kb = ksl * 8;
            uint32_t af[2][4];
#pragma unroll
            for (int mt = 0; mt < 2; mt++) {
                const int mb = warpM * 32 + mt * 16;
                af[mt][0] = As[cur][mb + g][kb + tg];
                af[mt][1] = As[cur][mb + 8 + g][kb + tg];
                af[mt][2] = As[cur][mb + g][kb + 4 + tg];
                af[mt][3] = As[cur][mb + 8 + g][kb + 4 + tg];
            }
#pragma unroll
            for (int nt = 0; nt < 8; nt++) {
                const int nb = warpN * 64 + nt * 8;
                uint32_t bf[2];
                bf[0] = Bs[cur][nb + g][kb + tg];
                bf[1] = Bs[cur][nb + g][kb + 4 + tg];
                mma_tf32(acc[0][nt], af[0], bf);
                mma_tf32(acc[1][nt], af[1], bf);
            }
        }
        __syncthreads();
        if (k < 63) {
            const int nxt = cur ^ 1;
            uint4 u;
            u.x = f2tf32(ra1.x); u.y = f2tf32(ra1.y); u.z = f2tf32(ra1.z); u.w = f2tf32(ra1.w);
            *(uint4*)&As[nxt][r1][c4] = u;
            u.x = f2tf32(ra2.x); u.y = f2tf32(ra2.y); u.z = f2tf32(ra2.z); u.w = f2tf32(ra2.w);
            *(uint4*)&As[nxt][r2][c4] = u;
            u.x = f2tf32(rb1.x); u.y = f2tf32(rb1.y); u.z = f2tf32(rb1.z); u.w = f2tf32(rb1.w);
            *(uint4*)&Bs[nxt][r1][c4] = u;
            u.x = f2tf32(rb2.x); u.y = f2tf32(rb2.y); u.z = f2tf32(rb2.z); u.w = f2tf32(rb2.w);
            *(uint4*)&Bs[nxt][r2][c4] = u;
            __syncthreads();
        }
    }

#pragma unroll
    for (int nt = 0; nt < 8; nt++) {
        const int col = n0 + warpN * 64 + nt * 8 + 2 * tg;
        const float bias0 = bih[col] + bhh[col];
        const float bias1 = bih[col + 1] + bhh[col + 1];
#pragma unroll
        for (int mt = 0; mt < 2; mt++) {
            const int row = m0 + warpM * 32 + mt * 16 + g;
            float2 v0; v0.x = acc[mt][nt][0] + bias0; v0.y = acc[mt][nt][1] + bias1;
            *(float2*)&g_xpre[(size_t)row * G4 + col] = v0;
            float2 v1; v1.x = acc[mt][nt][2] + bias0; v1.y = acc[mt][nt][3] + bias1;
            *(float2*)&g_xpre[(size_t)(row + 8) * G4 + col] = v1;
        }
    }
}

// ---------------- grid-wide barrier: two-level tree, self-resetting ----------------
__device__ __forceinline__ void gbar(int cta) {
    __syncthreads();
    if (threadIdx.x == 0) {
        volatile unsigned* vgen = &g_gen;
        const unsigned gen0 = *vgen;      // stable until all arrive
        __threadfence();                   // publish h/c stores before arrival
        const int grp = cta >> 3;
        if (atomicAdd(&g_cnt1[grp], 1u) == 7u) {
            g_cnt1[grp] = 0u;
            __threadfence();
            if (atomicAdd(&g_cnt2, 1u) == 15u) {
                g_cnt2 = 0u;
                __threadfence();
                *vgen = gen0 + 1u;         // release
            } else {
                while (*vgen == gen0) { __nanosleep(16); }
            }
        } else {
            while (*vgen == gen0) { __nanosleep(16); }
        }
    }
    __syncthreads();
}

// ---------------- phase 2: persistent recurrence (tf32 mma, K-split x8) ----------------
// 128 CTAs x 256 threads (8 warps). CTA owns 32 gate-cols {g*1024 + cta*8 + u}.
// Warp w owns ks in [w*16, w*16+16) and computes ALL 4 m-tiles x 4 n-tiles:
//   - W fragment (smem LDS.64) reused across 4 m-tiles
//   - h (A) fragments load L2->regs directly via asm ld.global.cg.v4, ring-2 prefetch
// 8 partial buffers reduced in the gate phase.
#define PRE_STRIDE 34
#define PRE_BUF    (64 * PRE_STRIDE)
__global__ __launch_bounds__(256) void lstm_rec_k(
    const float* __restrict__ Whh, const float* __restrict__ h0,
    const float* __restrict__ c0, float* __restrict__ out) {
    extern __shared__ uint32_t smem[];
    uint32_t* W_s   = smem;                          // 32768 u32 (128 KB)
    float*    pre_s = (float*)(smem + 32768);        // 8 x [64][34] = 69632 B

    const int tid    = threadIdx.x;
    const int lane   = tid & 31;
    const int w      = tid >> 5;                     // 0..7 == ks octant
    const int cta    = blockIdx.x;
    const int hcbase = cta * 8;

    // ---- fill W fragments (one-time; layout: ((n*128+ks)*32+lane)*2 ) ----
    for (int idx = tid; idx < 16384; idx += 256) {
        const int li = idx & 31;
        const int ks = (idx >> 5) & 127;
        const int n  = idx >> 12;
        const size_t row = (size_t)(n * HID + hcbase + (li >> 2)) * HID;
        const int k = ks * 8 + (li & 3);
        W_s[idx * 2]     = f2tf32(__ldg(&Whh[row + k]));
        W_s[idx * 2 + 1] = f2tf32(__ldg(&Whh[row + k + 4]));
    }

    // ---- cell ownership: thread owns hcol u, batches {bq2, bq2+32} ----
    const int u   = tid & 7;
    const int bq2 = tid >> 3;                        // 0..31
    const int lane_f = (bq2 & 7) * 4 + (u & 3);
    const int jreg   = ((u >> 2) & 1) * 2 + ((bq2 >> 3) & 1);
    const int mtb0   = bq2 >> 4;                     // 0..1; second cell uses mtb0+2

    float c_r[2], h_r[2];
#pragma unroll
    for (int j = 0; j < 2; j++) {
        const int b   = bq2 + 32 * j;
        const int idx = b * HID + hcbase + u;
        c_r[j] = c0[idx];
        const float h = h0[idx];
        h_r[j] = h;
        g_hbuf[0][((size_t)((mtb0 + 2 * j) * 128 + cta) * 32 + lane_f) * 4 + jreg] =
            __uint_as_float(f2tf32(h));
    }

    gbar(cta);

    const int ks0 = w * 16;

    for (int t = 0; t < T_STEPS; t++) {
        const float* hin  = g_hbuf[t & 1];
        float*       hout = g_hbuf[(t + 1) & 1];

        // ---- prefetch x_pre for this step (independent of h; hidden under mma) ----
        float xpv[2][4];
        {
            const float* xp = g_xpre + (size_t)t * BATCH * G4;
#pragma unroll
            for (int j = 0; j < 2; j++) {
                const float* xb = xp + (size_t)(bq2 + 32 * j) * G4 + hcbase + u;
                xpv[j][0] = __ldg(xb);
                xpv[j][1] = __ldg(xb + HID);
                xpv[j][2] = __ldg(xb + 2 * HID);
                xpv[j][3] = __ldg(xb + 3 * HID);
            }
        }

        float acc[4][4][4];                          // [mt][n][reg]
#pragma unroll
        for (int mt = 0; mt < 4; mt++)
#pragma unroll
            for (int n = 0; n < 4; n++)
#pragma unroll
                for (int r = 0; r < 4; r++) acc[mt][n][r] = 0.0f;

        const char* hb = (const char*)hin + lane * 16;

        // ring-2 register prefetch: chunk = 2 ks x 4 mt = 8 x uint4
        uint4 ar[2][8];
#pragma unroll
        for (int c = 0; c < 2; c++)
#pragma unroll
            for (int mt = 0; mt < 4; mt++)
                ar[0][c * 4 + mt] = ldg128_cg(hb + (size_t)((mt * 128 + ks0 + c) * 512));

#pragma unroll
        for (int kc = 0; kc < 8; kc++) {
            const int cur = kc & 1;
            if (kc < 7) {
                const int ksn = ks0 + (kc + 1) * 2;
#pragma unroll
                for (int c = 0; c < 2; c++)
#pragma unroll
                    for (int mt = 0; mt < 4; mt++)
                        ar[cur ^ 1][c * 4 + mt] =
                            ldg128_cg(hb + (size_t)((mt * 128 + ksn + c) * 512));
            }
#pragma unroll
            for (int c = 0; c < 2; c++) {
                const int ksg = ks0 + kc * 2 + c;
#pragma unroll
                for (int n = 0; n < 4; n++) {
                    const uint2 bv = *(const uint2*)&W_s[((n * 128 + ksg) * 32 + lane) * 2];
#pragma unroll
                    for (int mt = 0; mt < 4; mt++)
                        mma_tf32(acc[mt][n], (const uint32_t*)&ar[cur][c * 4 + mt],
                                 (const uint32_t*)&bv);
                }
            }
        }

        // publish partials to this warp's buffer
        {
            float* pb = pre_s + w * PRE_BUF;
            const int rg = lane >> 2;
            const int cg = 2 * (lane & 3);
#pragma unroll
            for (int mt = 0; mt < 4; mt++) {
                const int rb = mt * 16 + rg;
#pragma unroll
                for (int n = 0; n < 4; n++) {
                    const int colb = n * 8 + cg;
                    float2 v0; v0.x = acc[mt][n][0]; v0.y = acc[mt][n][1];
                    *(float2*)&pb[rb * PRE_STRIDE + colb] = v0;
                    float2 v1; v1.x = acc[mt][n][2]; v1.y = acc[mt][n][3];
                    *(float2*)&pb[(rb + 8) * PRE_STRIDE + colb] = v1;
                }
            }
        }
        __syncthreads();

        // gate math + h/c update + stores (2 cells per thread); sum 8 partials
        float* orow = out + (size_t)t * BATCH * HID;
#pragma unroll
        for (int j = 0; j < 2; j++) {
            const int b = bq2 + 32 * j;
            float pi = xpv[j][0], pf = xpv[j][1], po = xpv[j][2], pg = xpv[j][3];
#pragma unroll
            for (int p = 0; p < 8; p++) {
                const float* pb = &pre_s[p * PRE_BUF + b * PRE_STRIDE];
                pi += pb[u];
                pf += pb[8 + u];
                po += pb[16 + u];
                pg += pb[24 + u];
            }
            const float ig = 1.0f / (1.0f + __expf(-pi));
            const float fg = 1.0f / (1.0f + __expf(-pf));
            const float og = 1.0f / (1.0f + __expf(-po));
            c_r[j] = fg * c_r[j] + ig * tanhf(pg);
            const float h = og * tanhf(c_r[j]);
            h_r[j] = h;
            hout[((size_t)((mtb0 + 2 * j) * 128 + cta) * 32 + lane_f) * 4 + jreg] =
                __uint_as_float(f2tf32(h));
            orow[b * HID + hcbase + u] = h;
        }

        gbar(cta);
    }

    // finals: out = [output | h_f | c_f]
    float* hf = out + (size_t)T_STEPS * BATCH * HID;
    float* cf = hf + BATCH * HID;
#pragma unroll
    for (int j = 0; j < 2; j++) {
        const int b = bq2 + 32 * j;
        hf[b * HID + hcbase + u] = h_r[j];
        cf[b * HID + hcbase + u] = c_r[j];
    }
}

// ---------------- launch ----------------
extern "C" void kernel_launch(void* const* d_in, const int* in_sizes, int n_in,
                              void* d_out, int out_size) {
    const float* input = (const float*)d_in[0];   // [T, B, I]
    const float* h0    = (const float*)d_in[1];   // [1, B, H]
    const float* c0    = (const float*)d_in[2];   // [1, B, H]
    const float* W_ih  = (const float*)d_in[3];   // [4H, I]
    const float* b_ih  = (const float*)d_in[4];   // [4H]
    const float* W_hh  = (const float*)d_in[5];   // [4H, H]
    const float* b_hh  = (const float*)d_in[6];   // [4H]
    float* out = (float*)d_out;

    // W_s (131072 B) + pre_s (8*64*34*4 = 69632 B) = 200704 B
    const int rec_smem = 131072 + 8 * PRE_BUF * 4;
    cudaFuncSetAttribute(lstm_rec_k, cudaFuncAttributeMaxDynamicSharedMemorySize, rec_smem);

    dim3 g1(G4 / 128, M1 / 128);   // (32, 256)
    gemm1_k<<<g1, 256>>>(input, W_ih, b_ih, b_hh);
    lstm_rec_k<<<NCTA, 256, rec_smem>>>(W_hh, h0, c0, out);
}

// round 8
// speedup vs baseline: 1.6421x; 1.6421x over previous
#include <cuda_runtime.h>
#include <cstdint>
#include <cstddef>

#define T_STEPS 512
#define BATCH   64
#define HID     1024
#define G4      4096
#define M1      (T_STEPS * BATCH)   // 32768
#define NCTA    128

// ---------------- device scratch (no allocs allowed) ----------------
__device__ float    g_xpre[(size_t)M1 * G4];      // 512 MB: [T*B, 4H]
__device__ float    g_hbuf[2][BATCH * HID];       // double-buffered h, A-fragment-major layout
__device__ unsigned g_cnt1[16];                   // tree barrier: 16 groups of 8 CTAs
__device__ unsigned g_cnt2;                       // tree barrier: root (16 leaders)
__device__ unsigned g_gen;                        // monotonic generation

// ---------------- helpers ----------------
__device__ __forceinline__ uint32_t f2tf32(float x) {
    uint32_t r;
    asm("cvt.rna.tf32.f32 %0, %1;" : "=r"(r) : "f"(x));
    return r;
}

__device__ __forceinline__ void mma_tf32(float* c, const uint32_t* a, const uint32_t* b) {
    asm volatile(
        "mma.sync.aligned.m16n8k8.row.col.f32.tf32.tf32.f32 "
        "{%0,%1,%2,%3}, {%4,%5,%6,%7}, {%8,%9}, {%0,%1,%2,%3};"
        : "+f"(c[0]), "+f"(c[1]), "+f"(c[2]), "+f"(c[3])
        : "r"(a[0]), "r"(a[1]), "r"(a[2]), "r"(a[3]), "r"(b[0]), "r"(b[1]));
}

__device__ __forceinline__ void cp_async16(uint32_t saddr, const void* gaddr) {
    asm volatile("cp.async.cg.shared.global [%0], [%1], 16;\n"
                 :: "r"(saddr), "l"(gaddr));
}
#define CP_COMMIT() asm volatile("cp.async.commit_group;\n" ::: "memory")
#define CP_WAIT2()  asm volatile("cp.async.wait_group 2;\n" ::: "memory")

// ---------------- phase 1: x_pre = input @ W_ih^T + b_ih + b_hh (tf32 mma) ----------------
// CTA tile 128x128, 8 warps in 4(M) x 2(N), warp tile 32x64. K-chunk 16, 2-stage pipeline.
__global__ __launch_bounds__(256) void gemm1_k(
    const float* __restrict__ A, const float* __restrict__ W,
    const float* __restrict__ bih, const float* __restrict__ bhh) {
    __shared__ uint32_t As[2][128][20];
    __shared__ uint32_t Bs[2][128][20];

    const int tid   = threadIdx.x;
    const int lane  = tid & 31;
    const int wid   = tid >> 5;
    const int warpM = wid & 3;
    const int warpN = wid >> 2;
    const int m0 = blockIdx.y * 128;
    const int n0 = blockIdx.x * 128;

    const int r1 = tid >> 2;
    const int r2 = r1 + 64;
    const int c4 = (tid & 3) * 4;

    float acc[2][8][4];
#pragma unroll
    for (int mt = 0; mt < 2; mt++)
#pragma unroll
        for (int nt = 0; nt < 8; nt++)
#pragma unroll
            for (int r = 0; r < 4; r++) acc[mt][nt][r] = 0.0f;

    const float* Ap1 = A + (size_t)(m0 + r1) * 1024 + c4;
    const float* Ap2 = A + (size_t)(m0 + r2) * 1024 + c4;
    const float* Wp1 = W + (size_t)(n0 + r1) * 1024 + c4;
    const float* Wp2 = W + (size_t)(n0 + r2) * 1024 + c4;

    const int g  = lane >> 2;
    const int tg = lane & 3;

    float4 ra1, ra2, rb1, rb2;

    ra1 = *(const float4*)(Ap1);
    ra2 = *(const float4*)(Ap2);
    rb1 = *(const float4*)(Wp1);
    rb2 = *(const float4*)(Wp2);
    {
        uint4 u;
        u.x = f2tf32(ra1.x); u.y = f2tf32(ra1.y); u.z = f2tf32(ra1.z); u.w = f2tf32(ra1.w);
        *(uint4*)&As[0][r1][c4] = u;
        u.x = f2tf32(ra2.x); u.y = f2tf32(ra2.y); u.z = f2tf32(ra2.z); u.w = f2tf32(ra2.w);
        *(uint4*)&As[0][r2][c4] = u;
        u.x = f2tf32(rb1.x); u.y = f2tf32(rb1.y); u.z = f2tf32(rb1.z); u.w = f2tf32(rb1.w);
        *(uint4*)&Bs[0][r1][c4] = u;
        u.x = f2tf32(rb2.x); u.y = f2tf32(rb2.y); u.z = f2tf32(rb2.z); u.w = f2tf32(rb2.w);
        *(uint4*)&Bs[0][r2][c4] = u;
    }
    __syncthreads();

    for (int k = 0; k < 64; k++) {
        if (k < 63) {
            const int off = (k + 1) * 16;
            ra1 = *(const float4*)(Ap1 + off);
            ra2 = *(const float4*)(Ap2 + off);
            rb1 = *(const float4*)(Wp1 + off);
            rb2 = *(const float4*)(Wp2 + off);
        }
        const int cur = k & 1;

#pragma unroll
        for (int ksl = 0; ksl < 2; ksl++) {
            const int kb = ksl * 8;
            uint32_t af[2][4];
#pragma unroll
            for (int mt = 0; mt < 2; mt++) {
                const int mb = warpM * 32 + mt * 16;
                af[mt][0] = As[cur][mb + g][kb + tg];
                af[mt][1] = As[cur][mb + 8 + g][kb + tg];
                af[mt][2] = As[cur][mb + g][kb + 4 + tg];
                af[mt][3] = As[cur][mb + 8 + g][kb + 4 + tg];
            }
#pragma unroll
            for (int nt = 0; nt < 8; nt++) {
                const int nb = warpN * 64 + nt * 8;
                uint32_t bf[2];
                bf[0] = Bs[cur][nb + g][kb + tg];
                bf[1] = Bs[cur][nb + g][kb + 4 + tg];
                mma_tf32(acc[0][nt], af[0], bf);
                mma_tf32(acc[1][nt], af[1], bf);
            }
        }
        __syncthreads();
        if (k < 63) {
            const int nxt = cur ^ 1;
            uint4 u;
            u.x = f2tf32(ra1.x); u.y = f2tf32(ra1.y); u.z = f2tf32(ra1.z); u.w = f2tf32(ra1.w);
            *(uint4*)&As[nxt][r1][c4] = u;
            u.x = f2tf32(ra2.x); u.y = f2tf32(ra2.y); u.z = f2tf32(ra2.z); u.w = f2tf32(ra2.w);
            *(uint4*)&As[nxt][r2][c4] = u;
            u.x = f2tf32(rb1.x); u.y = f2tf32(rb1.y); u.z = f2tf32(rb1.z); u.w = f2tf32(rb1.w);
            *(uint4*)&Bs[nxt][r1][c4] = u;
            u.x = f2tf32(rb2.x); u.y = f2tf32(rb2.y); u.z = f2tf32(rb2.z); u.w = f2tf32(rb2.w);
            *(uint4*)&Bs[nxt][r2][c4] = u;
            __syncthreads();
        }
    }

#pragma unroll
    for (int nt = 0; nt < 8; nt++) {
        const int col = n0 + warpN * 64 + nt * 8 + 2 * tg;
        const float bias0 = bih[col] + bhh[col];
        const float bias1 = bih[col + 1] + bhh[col + 1];
#pragma unroll
        for (int mt = 0; mt < 2; mt++) {
            const int row = m0 + warpM * 32 + mt * 16 + g;
            float2 v0; v0.x = acc[mt][nt][0] + bias0; v0.y = acc[mt][nt][1] + bias1;
            *(float2*)&g_xpre[(size_t)row * G4 + col] = v0;
            float2 v1; v1.x = acc[mt][nt][2] + bias0; v1.y = acc[mt][nt][3] + bias1;
            *(float2*)&g_xpre[(size_t)(row + 8) * G4 + col] = v1;
        }
    }
}

// ---------------- grid-wide barrier: two-level tree, self-resetting ----------------
__device__ __forceinline__ void gbar(int cta) {
    __syncthreads();
    if (threadIdx.x == 0) {
        volatile unsigned* vgen = &g_gen;
        const unsigned gen0 = *vgen;      // stable until all arrive
        __threadfence();                   // publish h/c stores before arrival
        const int grp = cta >> 3;
        if (atomicAdd(&g_cnt1[grp], 1u) == 7u) {
            g_cnt1[grp] = 0u;
            __threadfence();
            if (atomicAdd(&g_cnt2, 1u) == 15u) {
                g_cnt2 = 0u;
                __threadfence();
                *vgen = gen0 + 1u;         // release
            } else {
                while (*vgen == gen0) { __nanosleep(16); }
            }
        } else {
            while (*vgen == gen0) { __nanosleep(16); }
        }
    }
    __syncthreads();
}

// ---------------- phase 2: persistent recurrence (tf32 mma, 4 K-quarters x 2 m-pairs) ----------------
// 128 CTAs x 256 threads (8 warps). CTA owns 32 gate-cols {g*1024 + cta*8 + u}.
// Warp w: kh = w>>1 owns ks in [kh*32, kh*32+32); mtp = w&1 owns m-tiles {2*mtp, 2*mtp+1}.
// Each W fragment (LDS.64) reused across 2 m-tiles; A staged via cp.async ring-3.
// 4 partial buffers (one per K-quarter) reduced in the gate phase.
#define PRE_STRIDE 34
#define PRE_BUF    (64 * PRE_STRIDE)
__global__ __launch_bounds__(256) void lstm_rec_k(
    const float* __restrict__ Whh, const float* __restrict__ h0,
    const float* __restrict__ c0, float* __restrict__ out) {
    extern __shared__ uint32_t smem[];
    uint32_t* W_s   = smem;                          // 32768 u32 (128 KB)
    float*    pre_s = (float*)(smem + 32768);        // 4 x [64][34] = 34816 B
    uint32_t* hs    = smem + 32768 + 4 * PRE_BUF;    // 8 warps x 3 x 2KB = 48 KB

    const int tid    = threadIdx.x;
    const int lane   = tid & 31;
    const int w      = tid >> 5;                     // 0..7
    const int kh     = w >> 1;                       // K quarter (0..3)
    const int mtp    = w & 1;                        // m-pair (0..1)
    const int cta    = blockIdx.x;
    const int hcbase = cta * 8;

    // warp-private staging base (shared-space byte address), lane offset folded in
    const uint32_t hs_w = (uint32_t)__cvta_generic_to_shared(hs) + w * 6144 + lane * 16;

    // ---- fill W fragments (one-time; layout: ((n*128+ks)*32+lane)*2 ) ----
    for (int idx = tid; idx < 16384; idx += 256) {
        const int li = idx & 31;
        const int ks = (idx >> 5) & 127;
        const int n  = idx >> 12;
        const size_t row = (size_t)(n * HID + hcbase + (li >> 2)) * HID;
        const int k = ks * 8 + (li & 3);
        W_s[idx * 2]     = f2tf32(__ldg(&Whh[row + k]));
        W_s[idx * 2 + 1] = f2tf32(__ldg(&Whh[row + k + 4]));
    }

    // ---- cell ownership: thread owns hcol u, batches {bq2, bq2+32} ----
    const int u   = tid & 7;
    const int bq2 = tid >> 3;                        // 0..31
    const int lane_f = (bq2 & 7) * 4 + (u & 3);
    const int jreg   = ((u >> 2) & 1) * 2 + ((bq2 >> 3) & 1);
    const int mtb0   = bq2 >> 4;                     // 0..1; second cell uses mtb0+2

    float c_r[2], h_r[2];
#pragma unroll
    for (int j = 0; j < 2; j++) {
        const int b   = bq2 + 32 * j;
        const int idx = b * HID + hcbase + u;
        c_r[j] = c0[idx];
        const float h = h0[idx];
        h_r[j] = h;
        g_hbuf[0][((size_t)((mtb0 + 2 * j) * 128 + cta) * 32 + lane_f) * 4 + jreg] =
            __uint_as_float(f2tf32(h));
    }

    gbar(cta);

    const int ks0 = kh * 32;

    for (int t = 0; t < T_STEPS; t++) {
        const float* hin  = g_hbuf[t & 1];
        float*       hout = g_hbuf[(t + 1) & 1];

        // ---- prefetch x_pre for this step (independent of h; hidden under mma) ----
        float xpv[2][4];
        {
            const float* xp = g_xpre + (size_t)t * BATCH * G4;
#pragma unroll
            for (int j = 0; j < 2; j++) {
                const float* xb = xp + (size_t)(bq2 + 32 * j) * G4 + hcbase + u;
                xpv[j][0] = __ldg(xb);
                xpv[j][1] = __ldg(xb + HID);
                xpv[j][2] = __ldg(xb + 2 * HID);
                xpv[j][3] = __ldg(xb + 3 * HID);
            }
        }

        float acc[2][4][4];                          // [mtl][n][reg]
#pragma unroll
        for (int m = 0; m < 2; m++)
#pragma unroll
            for (int n = 0; n < 4; n++)
#pragma unroll
                for (int r = 0; r < 4; r++) acc[m][n][r] = 0.0f;

        // source base for this warp's A fragments
        const char* hb = (const char*)hin + lane * 16;

        // issue chunk kc2 (2 ks x 2 mtl = 2 KB) into ring buffer kc2 % 3
        // prologue: chunks 0,1
#pragma unroll
        for (int pc = 0; pc < 2; pc++) {
            const uint32_t dst = hs_w + (pc % 3) * 2048;
#pragma unroll
            for (int c = 0; c < 2; c++)
#pragma unroll
                for (int mtl = 0; mtl < 2; mtl++)
                    cp_async16(dst + (c * 2 + mtl) * 512,
                               hb + (size_t)(((mtp * 2 + mtl) * 128 + ks0 + pc * 2 + c) * 512));
            CP_COMMIT();
        }

#pragma unroll
        for (int kc = 0; kc < 16; kc++) {
            if (kc + 2 < 16) {
                const int kc2 = kc + 2;
                const uint32_t dst = hs_w + (kc2 % 3) * 2048;
#pragma unroll
                for (int c = 0; c < 2; c++)
#pragma unroll
                    for (int mtl = 0; mtl < 2; mtl++)
                        cp_async16(dst + (c * 2 + mtl) * 512,
                                   hb + (size_t)(((mtp * 2 + mtl) * 128 + ks0 + kc2 * 2 + c) * 512));
            }
            CP_COMMIT();
            CP_WAIT2();               // chunk kc resident
            __syncwarp();

            const uint32_t bufb = hs_w + (kc % 3) * 2048;
#pragma unroll
            for (int c = 0; c < 2; c++) {
                const int ksg = ks0 + kc * 2 + c;
                uint32_t af0[4], af1[4];
                asm volatile("ld.shared.v4.b32 {%0,%1,%2,%3}, [%4];"
                             : "=r"(af0[0]), "=r"(af0[1]), "=r"(af0[2]), "=r"(af0[3])
                             : "r"(bufb + (c * 2 + 0) * 512));
                asm volatile("ld.shared.v4.b32 {%0,%1,%2,%3}, [%4];"
                             : "=r"(af1[0]), "=r"(af1[1]), "=r"(af1[2]), "=r"(af1[3])
                             : "r"(bufb + (c * 2 + 1) * 512));
#pragma unroll
                for (int n = 0; n < 4; n++) {
                    const uint2 bv = *(const uint2*)&W_s[((n * 128 + ksg) * 32 + lane) * 2];
                    mma_tf32(acc[0][n], af0, (const uint32_t*)&bv);
                    mma_tf32(acc[1][n], af1, (const uint32_t*)&bv);
                }
            }
        }

        // publish partials to this K-quarter's buffer (rows disjoint between mtp warps)
        {
            float* pb = pre_s + kh * PRE_BUF;
            const int rg = lane >> 2;
            const int cg = 2 * (lane & 3);
#pragma unroll
            for (int mtl = 0; mtl < 2; mtl++) {
                const int rb = (mtp * 2 + mtl) * 16 + rg;
#pragma unroll
                for (int n = 0; n < 4; n++) {
                    const int colb = n * 8 + cg;
                    float2 v0; v0.x = acc[mtl][n][0]; v0.y = acc[mtl][n][1];
                    *(float2*)&pb[rb * PRE_STRIDE + colb] = v0;
                    float2 v1; v1.x = acc[mtl][n][2]; v1.y = acc[mtl][n][3];
                    *(float2*)&pb[(rb + 8) * PRE_STRIDE + colb] = v1;
                }
            }
        }
        __syncthreads();

        // gate math + h/c update + stores (2 cells per thread); sum 4 partials
        float* orow = out + (size_t)t * BATCH * HID;
#pragma unroll
        for (int j = 0; j < 2; j++) {
            const int b = bq2 + 32 * j;
            float pi = xpv[j][0], pf = xpv[j][1], po = xpv[j][2], pg = xpv[j][3];
#pragma unroll
            for (int p = 0; p < 4; p++) {
                const float* pb = &pre_s[p * PRE_BUF + b * PRE_STRIDE];
                pi += pb[u];
                pf += pb[8 + u];
                po += pb[16 + u];
                pg += pb[24 + u];
            }
            const float ig = 1.0f / (1.0f + __expf(-pi));
            const float fg = 1.0f / (1.0f + __expf(-pf));
            const float og = 1.0f / (1.0f + __expf(-po));
            c_r[j] = fg * c_r[j] + ig * tanhf(pg);
            const float h = og * tanhf(c_r[j]);
            h_r[j] = h;
            hout[((size_t)((mtb0 + 2 * j) * 128 + cta) * 32 + lane_f) * 4 + jreg] =
                __uint_as_float(f2tf32(h));
            orow[b * HID + hcbase + u] = h;
        }

        gbar(cta);
    }

    // finals: out = [output | h_f | c_f]
    float* hf = out + (size_t)T_STEPS * BATCH * HID;
    float* cf = hf + BATCH * HID;
#pragma unroll
    for (int j = 0; j < 2; j++) {
        const int b = bq2 + 32 * j;
        hf[b * HID + hcbase + u] = h_r[j];
        cf[b * HID + hcbase + u] = c_r[j];
    }
}

// ---------------- launch ----------------
extern "C" void kernel_launch(void* const* d_in, const int* in_sizes, int n_in,
                              void* d_out, int out_size) {
    const float* input = (const float*)d_in[0];   // [T, B, I]
    const float* h0    = (const float*)d_in[1];   // [1, B, H]
    const float* c0    = (const float*)d_in[2];   // [1, B, H]
    const float* W_ih  = (const float*)d_in[3];   // [4H, I]
    const float* b_ih  = (const float*)d_in[4];   // [4H]
    const float* W_hh  = (const float*)d_in[5];   // [4H, H]
    const float* b_hh  = (const float*)d_in[6];   // [4H]
    float* out = (float*)d_out;

    // W_s (131072 B) + pre_s (4*64*34*4 = 34816 B) + staging (49152 B) = 215040 B
    const int rec_smem = 131072 + 4 * PRE_BUF * 4 + 49152;
    cudaFuncSetAttribute(lstm_rec_k, cudaFuncAttributeMaxDynamicSharedMemorySize, rec_smem);

    dim3 g1(G4 / 128, M1 / 128);   // (32, 256)
    gemm1_k<<<g1, 256>>>(input, W_ih, b_ih, b_hh);
    lstm_rec_k<<<NCTA, 256, rec_smem>>>(W_hh, h0, c0, out);
}

// round 10
// speedup vs baseline: 1.9028x; 1.1588x over previous
#include <cuda_runtime.h>
#include <cuda_fp16.h>
#include <cstdint>
#include <cstddef>

#define T_STEPS 512
#define BATCH   64
#define HID     1024
#define G4      4096
#define M1      (T_STEPS * BATCH)   // 32768
#define NCTA    128

// ---------------- device scratch (no allocs allowed) ----------------
__device__ float    g_xpre[(size_t)M1 * G4];      // 512 MB: [T*B, 4H]
__device__ __half   g_hbuf[2][BATCH * HID];       // double-buffered h, fp16 A-fragment-major
__device__ unsigned g_cnt1[16];                   // tree barrier: 16 groups of 8 CTAs
__device__ unsigned g_cnt2;                       // tree barrier root
__device__ unsigned g_gen;                        // monotonic generation

// ---------------- helpers ----------------
__device__ __forceinline__ uint32_t f2tf32(float x) {
    uint32_t r;
    asm("cvt.rna.tf32.f32 %0, %1;" : "=r"(r) : "f"(x));
    return r;
}

__device__ __forceinline__ void mma_tf32(float* c, const uint32_t* a, const uint32_t* b) {
    asm volatile(
        "mma.sync.aligned.m16n8k8.row.col.f32.tf32.tf32.f32 "
        "{%0,%1,%2,%3}, {%4,%5,%6,%7}, {%8,%9}, {%0,%1,%2,%3};"
        : "+f"(c[0]), "+f"(c[1]), "+f"(c[2]), "+f"(c[3])
        : "r"(a[0]), "r"(a[1]), "r"(a[2]), "r"(a[3]), "r"(b[0]), "r"(b[1]));
}

// fp16 MMA, fp32 accumulate: D[16x8] += A[16x16] x B[16x8]
__device__ __forceinline__ void mma_f16(float* c, const uint32_t* a, const uint32_t* b) {
    asm volatile(
        "mma.sync.aligned.m16n8k16.row.col.f32.f16.f16.f32 "
        "{%0,%1,%2,%3}, {%4,%5,%6,%7}, {%8,%9}, {%0,%1,%2,%3};"
        : "+f"(c[0]), "+f"(c[1]), "+f"(c[2]), "+f"(c[3])
        : "r"(a[0]), "r"(a[1]), "r"(a[2]), "r"(a[3]), "r"(b[0]), "r"(b[1]));
}

__device__ __forceinline__ void cp_async16(uint32_t saddr, const void* gaddr) {
    asm volatile("cp.async.cg.shared.global [%0], [%1], 16;\n"
                 :: "r"(saddr), "l"(gaddr));
}
#define CP_COMMIT() asm volatile("cp.async.commit_group;\n" ::: "memory")
#define CP_WAIT2()  asm volatile("cp.async.wait_group 2;\n" ::: "memory")

// ---------------- phase 1: x_pre = input @ W_ih^T + b_ih + b_hh (tf32 mma) ----------------
// CTA tile 128x128, 8 warps in 4(M) x 2(N), warp tile 32x64. K-chunk 16, 2-stage pipeline.
__global__ __launch_bounds__(256) void gemm1_k(
    const float* __restrict__ A, const float* __restrict__ W,
    const float* __restrict__ bih, const float* __restrict__ bhh) {
    __shared__ uint32_t As[2][128][20];
    __shared__ uint32_t Bs[2][128][20];

    const int tid   = threadIdx.x;
    const int lane  = tid & 31;
    const int wid   = tid >> 5;
    const int warpM = wid & 3;
    const int warpN = wid >> 2;
    const int m0 = blockIdx.y * 128;
    const int n0 = blockIdx.x * 128;

    const int r1 = tid >> 2;
    const int r2 = r1 + 64;
    const int c4 = (tid & 3) * 4;

    float acc[2][8][4];
#pragma unroll
    for (int mt = 0; mt < 2; mt++)
#pragma unroll
        for (int nt = 0; nt < 8; nt++)
#pragma unroll
            for (int r = 0; r < 4; r++) acc[mt][nt][r] = 0.0f;

    const float* Ap1 = A + (size_t)(m0 + r1) * 1024 + c4;
    const float* Ap2 = A + (size_t)(m0 + r2) * 1024 + c4;
    const float* Wp1 = W + (size_t)(n0 + r1) * 1024 + c4;
    const float* Wp2 = W + (size_t)(n0 + r2) * 1024 + c4;

    const int g  = lane >> 2;
    const int tg = lane & 3;

    float4 ra1, ra2, rb1, rb2;
    ra1 = *(const float4*)(Ap1);
    ra2 = *(const float4*)(Ap2);
    rb1 = *(const float4*)(Wp1);
    rb2 = *(const float4*)(Wp2);
    {
        uint4 u;
        u.x = f2tf32(ra1.x); u.y = f2tf32(ra1.y); u.z = f2tf32(ra1.z); u.w = f2tf32(ra1.w);
        *(uint4*)&As[0][r1][c4] = u;
        u.x = f2tf32(ra2.x); u.y = f2tf32(ra2.y); u.z = f2tf32(ra2.z); u.w = f2tf32(ra2.w);
        *(uint4*)&As[0][r2][c4] = u;
        u.x = f2tf32(rb1.x); u.y = f2tf32(rb1.y); u.z = f2tf32(rb1.z); u.w = f2tf32(rb1.w);
        *(uint4*)&Bs[0][r1][c4] = u;
        u.x = f2tf32(rb2.x); u.y = f2tf32(rb2.y); u.z = f2tf32(rb2.z); u.w = f2tf32(rb2.w);
        *(uint4*)&Bs[0][r2][c4] = u;
    }
    __syncthreads();

    for (int k = 0; k < 64; k++) {
        if (k < 63) {
            const int off = (k + 1) * 16;
            ra1 = *(const float4*)(Ap1 + off);
            ra2 = *(const float4*)(Ap2 + off);
            rb1 = *(const float4*)(Wp1 + off);
            rb2 = *(const float4*)(Wp2 + off);
        }
        const int cur = k & 1;

#pragma unroll
        for (int ksl = 0; ksl < 2; ksl++) {
            const int kb = ksl * 8;
            uint32_t af[2][4];
#pragma unroll
            for (int mt = 0; mt < 2; mt++) {
                const int mb = warpM * 32 + mt * 16;
                af[mt][0] = As[cur][mb + g][kb + tg];
                af[mt][1] = As[cur][mb + 8 + g][kb + tg];
                af[mt][2] = As[cur][mb + g][kb + 4 + tg];
                af[mt][3] = As[cur][mb + 8 + g][kb + 4 + tg];
            }
#pragma unroll
            for (int nt = 0; nt < 8; nt++) {
                const int nb = warpN * 64 + nt * 8;
                uint32_t bf[2];
                bf[0] = Bs[cur][nb + g][kb + tg];
                bf[1] = Bs[cur][nb + g][kb + 4 + tg];
                mma_tf32(acc[0][nt], af[0], bf);
                mma_tf32(acc[1][nt], af[1], bf);
            }
        }
        __syncthreads();
        if (k < 63) {
            const int nxt = cur ^ 1;
            uint4 u;
            u.x = f2tf32(ra1.x); u.y = f2tf32(ra1.y); u.z = f2tf32(ra1.z); u.w = f2tf32(ra1.w);
            *(uint4*)&As[nxt][r1][c4] = u;
            u.x = f2tf32(ra2.x); u.y = f2tf32(ra2.y); u.z = f2tf32(ra2.z); u.w = f2tf32(ra2.w);
            *(uint4*)&As[nxt][r2][c4] = u;
            u.x = f2tf32(rb1.x); u.y = f2tf32(rb1.y); u.z = f2tf32(rb1.z); u.w = f2tf32(rb1.w);
            *(uint4*)&Bs[nxt][r1][c4] = u;
            u.x = f2tf32(rb2.x); u.y = f2tf32(rb2.y); u.z = f2tf32(rb2.z); u.w = f2tf32(rb2.w);
            *(uint4*)&Bs[nxt][r2][c4] = u;
            __syncthreads();
        }
    }

#pragma unroll
    for (int nt = 0; nt < 8; nt++) {
        const int col = n0 + warpN * 64 + nt * 8 + 2 * tg;
        const float bias0 = bih[col] + bhh[col];
        const float bias1 = bih[col + 1] + bhh[col + 1];
#pragma unroll
        for (int mt = 0; mt < 2; mt++) {
            const int row = m0 + warpM * 32 + mt * 16 + g;
            float2 v0; v0.x = acc[mt][nt][0] + bias0; v0.y = acc[mt][nt][1] + bias1;
            *(float2*)&g_xpre[(size_t)row * G4 + col] = v0;
            float2 v1; v1.x = acc[mt][nt][2] + bias0; v1.y = acc[mt][nt][3] + bias1;
            *(float2*)&g_xpre[(size_t)(row + 8) * G4 + col] = v1;
        }
    }
}

// ---------------- grid-wide barrier: two-level tree, self-resetting ----------------
__device__ __forceinline__ void gbar(int cta) {
    __syncthreads();
    if (threadIdx.x == 0) {
        volatile unsigned* vgen = &g_gen;
        const unsigned gen0 = *vgen;
        __threadfence();
        const int grp = cta >> 3;
        if (atomicAdd(&g_cnt1[grp], 1u) == 7u) {
            g_cnt1[grp] = 0u;
            __threadfence();
            if (atomicAdd(&g_cnt2, 1u) == 15u) {
                g_cnt2 = 0u;
                __threadfence();
                *vgen = gen0 + 1u;
            } else {
                while (*vgen == gen0) { __nanosleep(16); }
            }
        } else {
            while (*vgen == gen0) { __nanosleep(16); }
        }
    }
    __syncthreads();
}

// ---------------- fp16 A-fragment addressing ----------------
// m16n8k16 A fragment (row-major): lane (g=l>>2, tg=l&3) holds 4 b32 (8 halves):
//   a0=(g, 2tg|2tg+1) a1=(g+8, ..) a2=(g, 2tg+8|+9) a3=(g+8, ..)
// h element (b,k): mt=b>>4, ks=k>>4, lane=(b&7)*4+((k>>1)&3),
//   reg j=((k>>3)&1)*2+((b>>3)&1), half=k&1
// byte offset = ((mt*64+ks)*32 + lane)*16 + j*4 + half*2
__device__ __forceinline__ uint32_t hfrag_off(int b, int k) {
    return (uint32_t)((((b >> 4) * 64 + (k >> 4)) * 32 + (b & 7) * 4 + ((k >> 1) & 3)) * 16
                      + (((k >> 3) & 1) * 2 + ((b >> 3) & 1)) * 4 + (k & 1) * 2);
}

// ---------------- phase 2: persistent recurrence (fp16 mma, 4 K-quarters x 2 m-pairs) ----------------
// 128 CTAs x 256 threads (8 warps). CTA owns 32 gate-cols {g*1024 + cta*8 + u}.
// K = 1024 = 64 k16-blocks. Warp w: kh=w>>1 owns ks in [kh*16, kh*16+16); mtp=w&1 owns
// m-tiles {2mtp, 2mtp+1}. W fragments (fp16, LDS.64) reused across 2 m-tiles; A staged
// via cp.async ring-3 (2 KB chunks). 4 partial buffers reduced in the gate phase.
#define PRE_STRIDE 34
#define PRE_BUF    (64 * PRE_STRIDE)
__global__ __launch_bounds__(256) void lstm_rec_k(
    const float* __restrict__ Whh, const float* __restrict__ h0,
    const float* __restrict__ c0, float* __restrict__ out) {
    extern __shared__ uint32_t smem[];
    uint32_t* W_s   = smem;                          // 16384 u32 (64 KB) fp16 b-fragments
    float*    pre_s = (float*)(smem + 16384);        // 4 x [64][34] = 34816 B
    uint32_t* hs    = smem + 16384 + 4 * PRE_BUF;    // 8 warps x 3 x 2KB = 48 KB

    const int tid    = threadIdx.x;
    const int lane   = tid & 31;
    const int w      = tid >> 5;                     // 0..7
    const int kh     = w >> 1;                       // K quarter (0..3)
    const int mtp    = w & 1;                        // m-pair (0..1)
    const int cta    = blockIdx.x;
    const int hcbase = cta * 8;

    const uint32_t hs_w = (uint32_t)__cvta_generic_to_shared(hs) + w * 6144 + lane * 16;

    // ---- fill W b-fragments (one-time), fp16 ----
    // entry (nt 0..3, ks 0..63, lane): b0 = W[nt*H+hcbase+g][16ks+2tg, +1],
    //                                  b1 = W[..][16ks+2tg+8, +9]   (g=lane>>2, tg=lane&3)
    for (int e = tid; e < 8192; e += 256) {
        const int li = e & 31;
        const int ks = (e >> 5) & 63;
        const int nt = e >> 11;
        const int g  = li >> 2;
        const int tg = li & 3;
        const float* wr = Whh + (size_t)(nt * HID + hcbase + g) * HID + ks * 16 + 2 * tg;
        __half2 b0 = __floats2half2_rn(__ldg(wr),     __ldg(wr + 1));
        __half2 b1 = __floats2half2_rn(__ldg(wr + 8), __ldg(wr + 9));
        W_s[e * 2]     = *(uint32_t*)&b0;
        W_s[e * 2 + 1] = *(uint32_t*)&b1;
    }

    // ---- cell ownership: thread owns hcol u, batches {bq2, bq2+32} ----
    const int u   = tid & 7;
    const int bq2 = tid >> 3;                        // 0..31

    float c_r[2], h_r[2];
#pragma unroll
    for (int j = 0; j < 2; j++) {
        const int b   = bq2 + 32 * j;
        const int idx = b * HID + hcbase + u;
        c_r[j] = c0[idx];
        const float h = h0[idx];
        h_r[j] = h;
        *(__half*)((char*)g_hbuf[0] + hfrag_off(b, hcbase + u)) = __float2half_rn(h);
    }

    gbar(cta);

    const int ks0 = kh * 16;

    for (int t = 0; t < T_STEPS; t++) {
        const char*  hin = (const char*)g_hbuf[t & 1];
        __half*     hout = g_hbuf[(t + 1) & 1];

        // ---- prefetch x_pre for this step (independent of h; hidden under mma) ----
        float xpv[2][4];
        {
            const float* xp = g_xpre + (size_t)t * BATCH * G4;
#pragma unroll
            for (int j = 0; j < 2; j++) {
                const float* xb = xp + (size_t)(bq2 + 32 * j) * G4 + hcbase + u;
                xpv[j][0] = __ldg(xb);
                xpv[j][1] = __ldg(xb + HID);
                xpv[j][2] = __ldg(xb + 2 * HID);
                xpv[j][3] = __ldg(xb + 3 * HID);
            }
        }

        float acc[2][4][4];                          // [mtl][n][reg]
#pragma unroll
        for (int m = 0; m < 2; m++)
#pragma unroll
            for (int n = 0; n < 4; n++)
#pragma unroll
                for (int r = 0; r < 4; r++) acc[m][n][r] = 0.0f;

        const char* hb = hin + lane * 16;

        // chunk = 2 ks x 2 mtl = 2 KB into ring slot kc % 3; prologue: chunks 0,1
#pragma unroll
        for (int pc = 0; pc < 2; pc++) {
            const uint32_t dst = hs_w + (pc % 3) * 2048;
#pragma unroll
            for (int c = 0; c < 2; c++)
#pragma unroll
                for (int mtl = 0; mtl < 2; mtl++)
                    cp_async16(dst + (c * 2 + mtl) * 512,
                               hb + (size_t)(((mtp * 2 + mtl) * 64 + ks0 + pc * 2 + c) * 512));
            CP_COMMIT();
        }

#pragma unroll
        for (int kc = 0; kc < 8; kc++) {
            if (kc + 2 < 8) {
                const int kc2 = kc + 2;
                const uint32_t dst = hs_w + (kc2 % 3) * 2048;
#pragma unroll
                for (int c = 0; c < 2; c++)
#pragma unroll
                    for (int mtl = 0; mtl < 2; mtl++)
                        cp_async16(dst + (c * 2 + mtl) * 512,
                                   hb + (size_t)(((mtp * 2 + mtl) * 64 + ks0 + kc2 * 2 + c) * 512));
            }
            CP_COMMIT();
            CP_WAIT2();               // chunk kc resident
            __syncwarp();

            const uint32_t bufb = hs_w + (kc % 3) * 2048;
#pragma unroll
            for (int c = 0; c < 2; c++) {
                const int ksg = ks0 + kc * 2 + c;
                uint32_t af0[4], af1[4];
                asm volatile("ld.shared.v4.b32 {%0,%1,%2,%3}, [%4];"
                             : "=r"(af0[0]), "=r"(af0[1]), "=r"(af0[2]), "=r"(af0[3])
                             : "r"(bufb + (c * 2 + 0) * 512));
                asm volatile("ld.shared.v4.b32 {%0,%1,%2,%3}, [%4];"
                             : "=r"(af1[0]), "=r"(af1[1]), "=r"(af1[2]), "=r"(af1[3])
                             : "r"(bufb + (c * 2 + 1) * 512));
#pragma unroll
                for (int n = 0; n < 4; n++) {
                    const uint2 bv = *(const uint2*)&W_s[((n * 64 + ksg) * 32 + lane) * 2];
                    mma_f16(acc[0][n], af0, (const uint32_t*)&bv);
                    mma_f16(acc[1][n], af1, (const uint32_t*)&bv);
                }
            }
        }

        // publish partials to this K-quarter's buffer (rows disjoint between mtp warps)
        {
            float* pb = pre_s + kh * PRE_BUF;
            const int rg = lane >> 2;
            const int cg = 2 * (lane & 3);
#pragma unroll
            for (int mtl = 0; mtl < 2; mtl++) {
                const int rb = (mtp * 2 + mtl) * 16 + rg;
#pragma unroll
                for (int n = 0; n < 4; n++) {
                    const int colb = n * 8 + cg;
                    float2 v0; v0.x = acc[mtl][n][0]; v0.y = acc[mtl][n][1];
                    *(float2*)&pb[rb * PRE_STRIDE + colb] = v0;
                    float2 v1; v1.x = acc[mtl][n][2]; v1.y = acc[mtl][n][3];
                    *(float2*)&pb[(rb + 8) * PRE_STRIDE + colb] = v1;
                }
            }
        }
        __syncthreads();

        // gate math + h/c update + stores (2 cells per thread); sum 4 partials
        float* orow = out + (size_t)t * BATCH * HID;
#pragma unroll
        for (int j = 0; j < 2; j++) {
            const int b = bq2 + 32 * j;
            float pi = xpv[j][0], pf = xpv[j][1], po = xpv[j][2], pg = xpv[j][3];
#pragma unroll
            for (int p = 0; p < 4; p++) {
                const float* pb = &pre_s[p * PRE_BUF + b * PRE_STRIDE];
                pi += pb[u];
                pf += pb[8 + u];
                po += pb[16 + u];
                pg += pb[24 + u];
            }
            const float ig = 1.0f / (1.0f + __expf(-pi));
            const float fg = 1.0f / (1.0f + __expf(-pf));
            const float og = 1.0f / (1.0f + __expf(-po));
            c_r[j] = fg * c_r[j] + ig * tanhf(pg);
            const float h = og * tanhf(c_r[j]);
            h_r[j] = h;
            *(__half*)((char*)hout + hfrag_off(b, hcbase + u)) = __float2half_rn(h);
            orow[b * HID + hcbase + u] = h;
        }

        gbar(cta);
    }

    // finals: out = [output | h_f | c_f]
    float* hf = out + (size_t)T_STEPS * BATCH * HID;
    float* cf = hf + BATCH * HID;
#pragma unroll
    for (int j = 0; j < 2; j++) {
        const int b = bq2 + 32 * j;
        hf[b * HID + hcbase + u] = h_r[j];
        cf[b * HID + hcbase + u] = c_r[j];
    }
}

// ---------------- launch ----------------
extern "C" void kernel_launch(void* const* d_in, const int* in_sizes, int n_in,
                              void* d_out, int out_size) {
    const float* input = (const float*)d_in[0];   // [T, B, I]
    const float* h0    = (const float*)d_in[1];   // [1, B, H]
    const float* c0    = (const float*)d_in[2];   // [1, B, H]
    const float* W_ih  = (const float*)d_in[3];   // [4H, I]
    const float* b_ih  = (const float*)d_in[4];   // [4H]
    const float* W_hh  = (const float*)d_in[5];   // [4H, H]
    const float* b_hh  = (const float*)d_in[6];   // [4H]
    float* out = (float*)d_out;

    // W_s (65536 B) + pre_s (34816 B) + staging (49152 B) = 149504 B
    const int rec_smem = 65536 + 4 * PRE_BUF * 4 + 49152;
    cudaFuncSetAttribute(lstm_rec_k, cudaFuncAttributeMaxDynamicSharedMemorySize, rec_smem);

    dim3 g1(G4 / 128, M1 / 128);   // (32, 256)
    gemm1_k<<<g1, 256>>>(input, W_ih, b_ih, b_hh);
    lstm_rec_k<<<NCTA, 256, rec_smem>>>(W_hh, h0, c0, out);
}